// round 14
// baseline (speedup 1.0000x reference)
#include <cuda_runtime.h>
#include <cuda_fp16.h>
#include <stdint.h>
#include <math.h>

#define BATCH 4096
#define NROWS 8192
#define DIM   128
#define INV_T 2.0f            // 1 / 0.5
#define NTILE 64              // 8192 / 128

#define BM 128
#define BN 128
#define NTHR 256
#define NCTA  (64 * 33)       // total k_main CTAs (incl. skip CTAs)

#define ROWB 288              // 256B fp16 row data + 32B pad (bank-stagger 8)
#define ROW8 36               // ROWB / 8 (ull units)
#define TILE_SMEM (BM * ROWB) // 36864 bytes per tile buffer
#define SMEM_TOTAL (2 * TILE_SMEM)   // 73728 -> 2 CTAs/SM

#define E2 7.3890560989306495f

typedef unsigned long long ull;

// ---------------- device scratch (allocation-free) ----------------
// fp16 normalized rows; within each 16-k group, slot order
// [k0 k1 k8 k9 | k2 k3 k10 k11 | k4 k5 k12 k13 | k6 k7 k14 k15]
__device__ __align__(16) __half g_zh[NROWS * DIM];
__device__ float g_pos[BATCH];
__device__ float g_denom[NROWS];
__device__ int   g_done;      // completion counter (reset by last CTA)

// ---------------- helpers ----------------
__device__ __forceinline__ uint32_t sptr(const void* p) {
    uint32_t a;
    asm("{ .reg .u64 t; cvta.to.shared.u64 t, %1; cvt.u32.u64 %0, t; }"
        : "=r"(a) : "l"(p));
    return a;
}
__device__ __forceinline__ uint32_t lo32(ull v) { return (uint32_t)v; }
__device__ __forceinline__ uint32_t hi32(ull v) { return (uint32_t)(v >> 32); }
__device__ __forceinline__ ull pack2(float lo, float hi) {
    ull r;
    asm("mov.b64 %0, {%1, %2};" : "=l"(r) : "f"(lo), "f"(hi));
    return r;
}
__device__ __forceinline__ void unpack2(ull v, float &lo, float &hi) {
    asm("mov.b64 {%0, %1}, %2;" : "=f"(lo), "=f"(hi) : "l"(v));
}
__device__ __forceinline__ ull fma2n(ull a, ull b, ull c) {
    ull d;
    asm("fma.rn.f32x2 %0, %1, %2, %3;" : "=l"(d) : "l"(a), "l"(b), "l"(c));
    return d;
}
__device__ __forceinline__ ull mul2(ull a, ull b) {
    ull d;
    asm("mul.rn.f32x2 %0, %1, %2;" : "=l"(d) : "l"(a), "l"(b));
    return d;
}
__device__ __forceinline__ ull add2(ull a, ull b) {
    ull d;
    asm("add.rn.f32x2 %0, %1, %2;" : "=l"(d) : "l"(a), "l"(b));
    return d;
}

// mma.sync m16n8k16 fp16 -> fp32: c += a * b
__device__ __forceinline__ void mma_f16(float* c, uint32_t a0, uint32_t a1,
                                        uint32_t a2, uint32_t a3,
                                        uint32_t b0, uint32_t b1) {
    asm volatile(
        "mma.sync.aligned.m16n8k16.row.col.f32.f16.f16.f32 "
        "{%0,%1,%2,%3}, {%4,%5,%6,%7}, {%8,%9}, {%0,%1,%2,%3};"
        : "+f"(c[0]), "+f"(c[1]), "+f"(c[2]), "+f"(c[3])
        : "r"(a0), "r"(a1), "r"(a2), "r"(a3), "r"(b0), "r"(b1));
}

#define CP_ASYNC16(dst_u32, src_ptr) \
    asm volatile("cp.async.cg.shared.global [%0], [%1], 16;" \
                 :: "r"(dst_u32), "l"(src_ptr) : "memory")
#define CP_COMMIT() asm volatile("cp.async.commit_group;" ::: "memory")
#define CP_WAIT1()  asm volatile("cp.async.wait_group 1;" ::: "memory")
#define CP_WAIT0()  asm volatile("cp.async.wait_group 0;" ::: "memory")

// stage one K-half (8 of 16 16B-chunks per row) of a 128-row fp16 tile
__device__ __forceinline__ void stage_half(char* dst, const __half* src,
                                           int tid, int half) {
    #pragma unroll
    for (int i = tid; i < 1024; i += NTHR) {
        int row = i >> 3;
        int cc  = (i & 7) + half * 8;
        uint32_t d = sptr(dst + row * ROWB + cc * 16);
        const char* s = (const char*)(src + (size_t)row * DIM) + cc * 16;
        CP_ASYNC16(d, s);
    }
}

// packed exp(2s): degree-6 Taylor on y=s/2, then two squarings
__device__ __forceinline__ ull exp2s_p(ull s) {
    const ull C720 = pack2(1.38888888889e-3f, 1.38888888889e-3f);
    const ull C120 = pack2(8.33333333333e-3f, 8.33333333333e-3f);
    const ull C24  = pack2(4.16666666667e-2f, 4.16666666667e-2f);
    const ull C6   = pack2(1.66666666667e-1f, 1.66666666667e-1f);
    const ull CH   = pack2(0.5f, 0.5f);
    const ull C1   = pack2(1.0f, 1.0f);
    ull y = mul2(s, CH);
    ull p = fma2n(C720, y, C120);
    p = fma2n(p, y, C24);
    p = fma2n(p, y, C6);
    p = fma2n(p, y, CH);
    p = fma2n(p, y, C1);
    p = fma2n(p, y, C1);     // ~= exp(y)
    p = mul2(p, p);          // exp(s)
    return mul2(p, p);       // exp(2s)
}

// fp16 row store with mma slot permutation
__device__ __forceinline__ void store_row(__half* dstrow, const float* vv, int lane) {
    #pragma unroll
    for (int c = 0; c < 4; c += 2) {
        int k = 4 * lane + c;
        int K16 = k >> 4, pp = (k & 15) >> 1;
        int slot = K16 * 16 + (pp & 3) * 4 + ((pp >> 2) << 1);
        *(__half2*)(dstrow + slot) = __floats2half2_rn(vv[c], vv[c + 1]);
    }
}

// ---------------- k_norm: paired rows (b, b+BATCH) per warp ----------------
__global__ void k_norm(const float* __restrict__ ei, const float* __restrict__ ej) {
    int b    = (blockIdx.x * blockDim.x + threadIdx.x) >> 5;
    int lane = threadIdx.x & 31;
    if (b >= BATCH) return;

    float4 vi = ((const float4*)(ei + (size_t)b * DIM))[lane];
    float4 vj = ((const float4*)(ej + (size_t)b * DIM))[lane];
    float ssi = vi.x*vi.x + vi.y*vi.y + vi.z*vi.z + vi.w*vi.w;
    float ssj = vj.x*vj.x + vj.y*vj.y + vj.z*vj.z + vj.w*vj.w;
    float dt  = vi.x*vj.x + vi.y*vj.y + vi.z*vj.z + vi.w*vj.w;
    #pragma unroll
    for (int o = 16; o; o >>= 1) {
        ssi += __shfl_xor_sync(0xffffffffu, ssi, o);
        ssj += __shfl_xor_sync(0xffffffffu, ssj, o);
        dt  += __shfl_xor_sync(0xffffffffu, dt,  o);
    }
    float ni = fmaxf(sqrtf(ssi), 1e-12f);
    float nj = fmaxf(sqrtf(ssj), 1e-12f);
    if (lane == 0) {
        g_pos[b] = dt / (ni * nj);
        g_denom[b] = 0.0f;
        g_denom[b + BATCH] = 0.0f;
    }
    float si = 1.0f / ni, sj = 1.0f / nj;
    float wi[4] = { vi.x * si, vi.y * si, vi.z * si, vi.w * si };
    float wj[4] = { vj.x * sj, vj.y * sj, vj.z * sj, vj.w * sj };
    store_row(g_zh + (size_t)b * DIM, wi, lane);
    store_row(g_zh + (size_t)(b + BATCH) * DIM, wj, lane);
}

// ---------------- main: symmetric fp16 GEMM + packed exp + fused loss tail ----------------
// grid (64, 33): by==0 -> diagonal tile (bi,bi); by 1..32 -> pair {bi, (bi+by)&63}
// (by==32 works only for bi<32; others skip but still hit the completion counter).
__global__ void __launch_bounds__(NTHR, 2) k_main(float* __restrict__ out) {
    extern __shared__ char smem[];
    __shared__ int s_last;

    const int bi = blockIdx.x;
    const int by = blockIdx.y;
    const bool skip = (by == 32 && bi >= 32);
    const int tid  = threadIdx.x;

    if (!skip) {
        const int bj    = (bi + by) & (NTILE - 1);
        const bool diag = (by == 0);

        char* As = smem;
        char* Bs = smem + TILE_SMEM;

        const int wid  = tid >> 5;
        const int lane = tid & 31;
        const int g    = lane >> 2;         // 0..7
        const int q    = lane & 3;          // 0..3
        const int wm   = wid >> 2;          // 0..1  (M warp, 64 rows)
        const int wn   = wid & 3;           // 0..3  (N warp, 32 cols)
        const int rowStart = bi * BM;
        const int colStart = bj * BN;

        const __half* srcA = g_zh + (size_t)rowStart * DIM;
        const __half* srcB = g_zh + (size_t)colStart * DIM;

        stage_half(As, srcA, tid, 0);
        stage_half(Bs, srcB, tid, 0);
        CP_COMMIT();
        stage_half(As, srcA, tid, 1);
        stage_half(Bs, srcB, tid, 1);
        CP_COMMIT();

        const ull* As8 = (const ull*)As;
        const ull* Bs8 = (const ull*)Bs;

        float C[4][4][4];
        #pragma unroll
        for (int i = 0; i < 4; i++)
            #pragma unroll
            for (int j = 0; j < 4; j++)
                #pragma unroll
                for (int e = 0; e < 4; e++) C[i][j][e] = 0.0f;

        CP_WAIT1();
        __syncthreads();

        #pragma unroll
        for (int kh = 0; kh < 2; ++kh) {
            if (kh == 1) { CP_WAIT0(); __syncthreads(); }
            #pragma unroll
            for (int ki = 0; ki < 4; ++ki) {
                const int ks = kh * 4 + ki;          // K16-step 0..7
                ull alo[4], ahi[4], bv[4];
                #pragma unroll
                for (int i = 0; i < 4; i++) {
                    int r0 = wm * 64 + i * 16 + g;
                    alo[i] = As8[r0 * ROW8 + ks * 4 + q];
                    ahi[i] = As8[(r0 + 8) * ROW8 + ks * 4 + q];
                }
                #pragma unroll
                for (int j = 0; j < 4; j++) {
                    int n0 = wn * 32 + j * 8 + g;
                    bv[j] = Bs8[n0 * ROW8 + ks * 4 + q];
                }
                #pragma unroll
                for (int i = 0; i < 4; i++)
                    #pragma unroll
                    for (int j = 0; j < 4; j++)
                        mma_f16(C[i][j],
                                lo32(alo[i]), lo32(ahi[i]),
                                hi32(alo[i]), hi32(ahi[i]),
                                lo32(bv[j]),  hi32(bv[j]));
            }
        }

        // packed exp epilogue: row sums (always) + col sums (off-diag)
        ull rs2[4][2];           // [i][rowhalf], lanes = col parity
        ull cs2[4];              // [j], lanes = col parity
        #pragma unroll
        for (int i = 0; i < 4; i++) { rs2[i][0] = pack2(0.f, 0.f); rs2[i][1] = pack2(0.f, 0.f); }
        #pragma unroll
        for (int j = 0; j < 4; j++) cs2[j] = pack2(0.f, 0.f);

        #pragma unroll
        for (int i = 0; i < 4; i++)
            #pragma unroll
            for (int j = 0; j < 4; j++) {
                ull p0 = exp2s_p(pack2(C[i][j][0], C[i][j][1]));
                rs2[i][0] = add2(rs2[i][0], p0);
                cs2[j]    = add2(cs2[j], p0);
                ull p1 = exp2s_p(pack2(C[i][j][2], C[i][j][3]));
                rs2[i][1] = add2(rs2[i][1], p1);
                cs2[j]    = add2(cs2[j], p1);
            }

        __syncthreads();   // mma reads done; reuse smem for reductions
        float* red  = (float*)smem;            // [128][4] row partials per wn
        float* redc = (float*)smem + 512;      // [128][2] col partials per wm

        #pragma unroll
        for (int i = 0; i < 4; i++) {
            #pragma unroll
            for (int h = 0; h < 2; h++) {
                float lo, hi;
                unpack2(rs2[i][h], lo, hi);
                float v = lo + hi;
                v += __shfl_xor_sync(0xffffffffu, v, 1);
                v += __shfl_xor_sync(0xffffffffu, v, 2);
                if (q == 0) {
                    int row = wm * 64 + i * 16 + h * 8 + g;
                    red[row * 4 + wn] = v;
                }
            }
        }
        if (!diag) {
            #pragma unroll
            for (int j = 0; j < 4; j++) {
                float lo, hi;
                unpack2(cs2[j], lo, hi);
                #pragma unroll
                for (int o = 4; o <= 16; o <<= 1) {
                    lo += __shfl_xor_sync(0xffffffffu, lo, o);
                    hi += __shfl_xor_sync(0xffffffffu, hi, o);
                }
                if (g == 0) {
                    int col = wn * 32 + j * 8 + q * 2;
                    redc[col * 2 + wm]       = lo;
                    redc[(col + 1) * 2 + wm] = hi;
                }
            }
        }
        __syncthreads();

        if (tid < BM) {
            float s = red[tid * 4] + red[tid * 4 + 1] + red[tid * 4 + 2] + red[tid * 4 + 3];
            if (diag) s -= E2;   // remove diagonal exp(2*sim_rr) ~ e^2
            atomicAdd(&g_denom[rowStart + tid], s);
            if (!diag) {
                float c = redc[tid * 2] + redc[tid * 2 + 1];
                atomicAdd(&g_denom[colStart + tid], c);
            }
        }
    }

    // ---------------- completion counter + fused loss tail ----------------
    __syncthreads();
    if (tid == 0) {
        __threadfence();
        int old = atomicAdd(&g_done, 1);
        s_last = (old == NCTA - 1) ? 1 : 0;
    }
    __syncthreads();
    if (s_last) {
        float s = 0.0f;
        for (int r = tid; r < NROWS; r += NTHR) {
            float p = __ldcg(&g_pos[(r < BATCH) ? r : (r - BATCH)]);
            s += logf(__ldcg(&g_denom[r])) - p * INV_T;
        }
        float* red = (float*)smem;
        red[tid] = s;
        __syncthreads();
        #pragma unroll
        for (int st = 128; st; st >>= 1) {
            if (tid < st) red[tid] += red[tid + st];
            __syncthreads();
        }
        if (tid == 0) {
            out[0] = red[0] / (float)NROWS;
            g_done = 0;                // reset for graph replay determinism
        }
    }
}

extern "C" void kernel_launch(void* const* d_in, const int* in_sizes, int n_in,
                              void* d_out, int out_size) {
    const float* emb_i = (const float*)d_in[0];
    const float* emb_j = (const float*)d_in[1];
    float* out = (float*)d_out;
    (void)in_sizes; (void)n_in; (void)out_size;

    cudaFuncSetAttribute(k_main, cudaFuncAttributeMaxDynamicSharedMemorySize,
                         SMEM_TOTAL);

    k_norm<<<BATCH / 8, 256>>>(emb_i, emb_j);
    dim3 grid(NTILE, 33);
    k_main<<<grid, NTHR, SMEM_TOTAL>>>(out);
}

// round 15
// speedup vs baseline: 1.1875x; 1.1875x over previous
#include <cuda_runtime.h>
#include <cuda_fp16.h>
#include <stdint.h>
#include <math.h>

#define BATCH 4096
#define NROWS 8192
#define DIM   128
#define INV_T 2.0f            // 1 / 0.5
#define NTILE 64              // 8192 / 128

#define BM 128
#define BN 128
#define NTHR 256

#define ROWB 288              // 256B fp16 row data + 32B pad (bank-stagger 8)
#define ROW8 36               // ROWB / 8 (ull units)
#define TILE_SMEM (BM * ROWB) // 36864 bytes per tile buffer
#define SMEM_TOTAL (2 * TILE_SMEM)   // 73728 -> 2 CTAs/SM

#define E2 7.3890560989306495f

typedef unsigned long long ull;

// ---------------- device scratch (allocation-free) ----------------
// fp16 normalized rows; within each 16-k group, slot order
// [k0 k1 k8 k9 | k2 k3 k10 k11 | k4 k5 k12 k13 | k6 k7 k14 k15]
__device__ __align__(16) __half g_zh[NROWS * DIM];
__device__ float g_pos[BATCH];
__device__ float g_denom[NROWS];

// ---------------- helpers ----------------
__device__ __forceinline__ uint32_t sptr(const void* p) {
    uint32_t a;
    asm("{ .reg .u64 t; cvta.to.shared.u64 t, %1; cvt.u32.u64 %0, t; }"
        : "=r"(a) : "l"(p));
    return a;
}
__device__ __forceinline__ uint32_t lo32(ull v) { return (uint32_t)v; }
__device__ __forceinline__ uint32_t hi32(ull v) { return (uint32_t)(v >> 32); }

// mma.sync m16n8k16 fp16 -> fp32: c += a * b
__device__ __forceinline__ void mma_f16(float* c, uint32_t a0, uint32_t a1,
                                        uint32_t a2, uint32_t a3,
                                        uint32_t b0, uint32_t b1) {
    asm volatile(
        "mma.sync.aligned.m16n8k16.row.col.f32.f16.f16.f32 "
        "{%0,%1,%2,%3}, {%4,%5,%6,%7}, {%8,%9}, {%0,%1,%2,%3};"
        : "+f"(c[0]), "+f"(c[1]), "+f"(c[2]), "+f"(c[3])
        : "r"(a0), "r"(a1), "r"(a2), "r"(a3), "r"(b0), "r"(b1));
}

#define CP_ASYNC16(dst_u32, src_ptr) \
    asm volatile("cp.async.cg.shared.global [%0], [%1], 16;" \
                 :: "r"(dst_u32), "l"(src_ptr) : "memory")
#define CP_COMMIT() asm volatile("cp.async.commit_group;" ::: "memory")
#define CP_WAIT1()  asm volatile("cp.async.wait_group 1;" ::: "memory")
#define CP_WAIT0()  asm volatile("cp.async.wait_group 0;" ::: "memory")

// stage one K-half (8 of 16 16B-chunks per row) of a 128-row fp16 tile
__device__ __forceinline__ void stage_half(char* dst, const __half* src,
                                           int tid, int half) {
    #pragma unroll
    for (int i = tid; i < 1024; i += NTHR) {
        int row = i >> 3;
        int cc  = (i & 7) + half * 8;
        uint32_t d = sptr(dst + row * ROWB + cc * 16);
        const char* s = (const char*)(src + (size_t)row * DIM) + cc * 16;
        CP_ASYNC16(d, s);
    }
}

// exp(2s): degree-6 Taylor on s directly (|s|<=0.6 off-diag), one squaring.
// rel err <= 2.5e-6 off-diag; diag residual absorbed by exact-e2 subtraction.
__device__ __forceinline__ float exp2s(float s) {
    float p = fmaf(s, 1.38888888889e-3f, 8.33333333333e-3f);  // s/720 + 1/120
    p = fmaf(p, s, 4.16666666667e-2f);                        // + 1/24
    p = fmaf(p, s, 1.66666666667e-1f);                        // + 1/6
    p = fmaf(p, s, 0.5f);
    p = fmaf(p, s, 1.0f);
    p = fmaf(p, s, 1.0f);     // ~= exp(s)
    return p * p;             // exp(2s)
}

// fp16 row store with mma slot permutation
__device__ __forceinline__ void store_row(__half* dstrow, const float* vv, int lane) {
    #pragma unroll
    for (int c = 0; c < 4; c += 2) {
        int k = 4 * lane + c;
        int K16 = k >> 4, pp = (k & 15) >> 1;
        int slot = K16 * 16 + (pp & 3) * 4 + ((pp >> 2) << 1);
        *(__half2*)(dstrow + slot) = __floats2half2_rn(vv[c], vv[c + 1]);
    }
}

// ---------------- k_norm: paired rows (b, b+BATCH) per warp ----------------
__global__ void k_norm(const float* __restrict__ ei, const float* __restrict__ ej) {
    int b    = (blockIdx.x * blockDim.x + threadIdx.x) >> 5;
    int lane = threadIdx.x & 31;
    if (b >= BATCH) return;

    float4 vi = ((const float4*)(ei + (size_t)b * DIM))[lane];
    float4 vj = ((const float4*)(ej + (size_t)b * DIM))[lane];
    float ssi = vi.x*vi.x + vi.y*vi.y + vi.z*vi.z + vi.w*vi.w;
    float ssj = vj.x*vj.x + vj.y*vj.y + vj.z*vj.z + vj.w*vj.w;
    float dt  = vi.x*vj.x + vi.y*vj.y + vi.z*vj.z + vi.w*vj.w;
    #pragma unroll
    for (int o = 16; o; o >>= 1) {
        ssi += __shfl_xor_sync(0xffffffffu, ssi, o);
        ssj += __shfl_xor_sync(0xffffffffu, ssj, o);
        dt  += __shfl_xor_sync(0xffffffffu, dt,  o);
    }
    float ni = fmaxf(sqrtf(ssi), 1e-12f);
    float nj = fmaxf(sqrtf(ssj), 1e-12f);
    if (lane == 0) {
        g_pos[b] = dt / (ni * nj);
        g_denom[b] = 0.0f;
        g_denom[b + BATCH] = 0.0f;
    }
    float si = 1.0f / ni, sj = 1.0f / nj;
    float wi[4] = { vi.x * si, vi.y * si, vi.z * si, vi.w * si };
    float wj[4] = { vj.x * sj, vj.y * sj, vj.z * sj, vj.w * sj };
    store_row(g_zh + (size_t)b * DIM, wi, lane);
    store_row(g_zh + (size_t)(b + BATCH) * DIM, wj, lane);
}

// ---------------- main: symmetric (upper-triangle) fp16 GEMM + fused exp ----------------
// grid (64, 33): by==0 -> diagonal tile (bi,bi); by 1..32 -> pair {bi, (bi+by)&63}
// (by==32 valid only for bi<32). Row sums -> denom[bi rows]; col sums -> denom[bj rows].
__global__ void __launch_bounds__(NTHR, 2) k_main() {
    const int bi = blockIdx.x;
    const int by = blockIdx.y;
    if (by == 32 && bi >= 32) return;
    const int bj    = (bi + by) & (NTILE - 1);
    const bool diag = (by == 0);

    extern __shared__ char smem[];
    char* As = smem;
    char* Bs = smem + TILE_SMEM;

    const int tid  = threadIdx.x;
    const int wid  = tid >> 5;
    const int lane = tid & 31;
    const int g    = lane >> 2;         // 0..7
    const int q    = lane & 3;          // 0..3
    const int wm   = wid >> 2;          // 0..1  (M warp, 64 rows)
    const int wn   = wid & 3;           // 0..3  (N warp, 32 cols)
    const int rowStart = bi * BM;
    const int colStart = bj * BN;

    const __half* srcA = g_zh + (size_t)rowStart * DIM;
    const __half* srcB = g_zh + (size_t)colStart * DIM;

    // stage both tiles, split by K-half for load/compute overlap
    stage_half(As, srcA, tid, 0);
    stage_half(Bs, srcB, tid, 0);
    CP_COMMIT();
    stage_half(As, srcA, tid, 1);
    stage_half(Bs, srcB, tid, 1);
    CP_COMMIT();

    const ull* As8 = (const ull*)As;
    const ull* Bs8 = (const ull*)Bs;

    float C[4][4][4];
    #pragma unroll
    for (int i = 0; i < 4; i++)
        #pragma unroll
        for (int j = 0; j < 4; j++)
            #pragma unroll
            for (int e = 0; e < 4; e++) C[i][j][e] = 0.0f;

    CP_WAIT1();
    __syncthreads();

    #pragma unroll
    for (int kh = 0; kh < 2; ++kh) {
        if (kh == 1) { CP_WAIT0(); __syncthreads(); }
        #pragma unroll
        for (int ki = 0; ki < 4; ++ki) {
            const int ks = kh * 4 + ki;          // K16-step 0..7
            ull alo[4], ahi[4], bv[4];
            #pragma unroll
            for (int i = 0; i < 4; i++) {
                int r0 = wm * 64 + i * 16 + g;
                alo[i] = As8[r0 * ROW8 + ks * 4 + q];
                ahi[i] = As8[(r0 + 8) * ROW8 + ks * 4 + q];
            }
            #pragma unroll
            for (int j = 0; j < 4; j++) {
                int n0 = wn * 32 + j * 8 + g;
                bv[j] = Bs8[n0 * ROW8 + ks * 4 + q];
            }
            #pragma unroll
            for (int i = 0; i < 4; i++)
                #pragma unroll
                for (int j = 0; j < 4; j++)
                    mma_f16(C[i][j],
                            lo32(alo[i]), lo32(ahi[i]),
                            hi32(alo[i]), hi32(ahi[i]),
                            lo32(bv[j]),  hi32(bv[j]));
        }
    }

    // epilogue: exp(2*sim); row sums (always) + col sums (off-diag)
    float rs[4][2];                 // [i][rowhalf]
    float cs[8];                    // [j*2 + colparity]
    #pragma unroll
    for (int i = 0; i < 4; i++) { rs[i][0] = 0.0f; rs[i][1] = 0.0f; }
    #pragma unroll
    for (int e = 0; e < 8; e++) cs[e] = 0.0f;

    #pragma unroll
    for (int i = 0; i < 4; i++)
        #pragma unroll
        for (int j = 0; j < 4; j++)
            #pragma unroll
            for (int r = 0; r < 4; r++) {
                float ev = exp2s(C[i][j][r]);
                rs[i][r >> 1] += ev;
                cs[j * 2 + (r & 1)] += ev;
            }

    __syncthreads();   // all mma reads of As/Bs done; reuse smem for reductions
    float* red  = (float*)smem;            // [128][4] row partials per wn
    float* redc = (float*)smem + 512;      // [128][2] col partials per wm

    // row sums: reduce over q (cols within quad)
    #pragma unroll
    for (int i = 0; i < 4; i++) {
        #pragma unroll
        for (int h = 0; h < 2; h++) {
            float v = rs[i][h];
            v += __shfl_xor_sync(0xffffffffu, v, 1);
            v += __shfl_xor_sync(0xffffffffu, v, 2);
            if (q == 0) {
                int row = wm * 64 + i * 16 + h * 8 + g;
                red[row * 4 + wn] = v;
            }
        }
    }
    // col sums: reduce over g (rows within warp)
    if (!diag) {
        #pragma unroll
        for (int e = 0; e < 8; e++) {
            float v = cs[e];
            v += __shfl_xor_sync(0xffffffffu, v, 4);
            v += __shfl_xor_sync(0xffffffffu, v, 8);
            v += __shfl_xor_sync(0xffffffffu, v, 16);
            if (g == 0) {
                int col = wn * 32 + (e >> 1) * 8 + q * 2 + (e & 1);
                redc[col * 2 + wm] = v;
            }
        }
    }
    __syncthreads();

    if (tid < BM) {
        float s = red[tid * 4] + red[tid * 4 + 1] + red[tid * 4 + 2] + red[tid * 4 + 3];
        if (diag) s -= E2;   // remove diagonal exp(2*sim_rr) ~ e^2
        atomicAdd(&g_denom[rowStart + tid], s);
        if (!diag) {
            float c = redc[tid * 2] + redc[tid * 2 + 1];
            atomicAdd(&g_denom[colStart + tid], c);
        }
    }
}

// ---------------- final loss reduction ----------------
__global__ void k_loss(float* __restrict__ out) {
    int tid = threadIdx.x;
    float s = 0.0f;
    for (int r = tid; r < NROWS; r += 1024) {
        float p = g_pos[(r < BATCH) ? r : (r - BATCH)];
        s += logf(g_denom[r]) - p * INV_T;
    }
    __shared__ float red[1024];
    red[tid] = s;
    __syncthreads();
    #pragma unroll
    for (int st = 512; st; st >>= 1) {
        if (tid < st) red[tid] += red[tid + st];
        __syncthreads();
    }
    if (tid == 0) out[0] = red[0] / (float)NROWS;
}

extern "C" void kernel_launch(void* const* d_in, const int* in_sizes, int n_in,
                              void* d_out, int out_size) {
    const float* emb_i = (const float*)d_in[0];
    const float* emb_j = (const float*)d_in[1];
    float* out = (float*)d_out;
    (void)in_sizes; (void)n_in; (void)out_size;

    cudaFuncSetAttribute(k_main, cudaFuncAttributeMaxDynamicSharedMemorySize,
                         SMEM_TOTAL);

    k_norm<<<BATCH / 8, 256>>>(emb_i, emb_j);
    dim3 grid(NTILE, 33);
    k_main<<<grid, NTHR, SMEM_TOTAL>>>();
    k_loss<<<1, 1024>>>(out);
}

// round 16
// speedup vs baseline: 1.2385x; 1.0429x over previous
#include <cuda_runtime.h>
#include <cuda_fp16.h>
#include <stdint.h>
#include <math.h>

#define BATCH 4096
#define NROWS 8192
#define DIM   128
#define INV_T 2.0f            // 1 / 0.5
#define NTILE 64              // 8192 / 128

#define BM 128
#define BN 128
#define NTHR 256

#define ROWB 288              // 256B fp16 row data + 32B pad (bank-stagger 8)
#define ROW8 36               // ROWB / 8 (ull units)
#define TILE_SMEM (BM * ROWB) // 36864 bytes per tile buffer
#define SMEM_TOTAL (2 * TILE_SMEM)   // 73728 -> 2 CTAs/SM

#define E2 7.3890560989306495f

typedef unsigned long long ull;

// ---------------- device scratch (allocation-free) ----------------
// fp16 normalized rows; within each 16-k group, slot order
// [k0 k1 k8 k9 | k2 k3 k10 k11 | k4 k5 k12 k13 | k6 k7 k14 k15]
__device__ __align__(16) __half g_zh[NROWS * DIM];
__device__ float g_pos[BATCH];
__device__ float g_denom[NROWS];

// ---------------- helpers ----------------
__device__ __forceinline__ uint32_t sptr(const void* p) {
    uint32_t a;
    asm("{ .reg .u64 t; cvta.to.shared.u64 t, %1; cvt.u32.u64 %0, t; }"
        : "=r"(a) : "l"(p));
    return a;
}
__device__ __forceinline__ uint32_t lo32(ull v) { return (uint32_t)v; }
__device__ __forceinline__ uint32_t hi32(ull v) { return (uint32_t)(v >> 32); }

// mma.sync m16n8k16 fp16 -> fp32: c += a * b
__device__ __forceinline__ void mma_f16(float* c, uint32_t a0, uint32_t a1,
                                        uint32_t a2, uint32_t a3,
                                        uint32_t b0, uint32_t b1) {
    asm volatile(
        "mma.sync.aligned.m16n8k16.row.col.f32.f16.f16.f32 "
        "{%0,%1,%2,%3}, {%4,%5,%6,%7}, {%8,%9}, {%0,%1,%2,%3};"
        : "+f"(c[0]), "+f"(c[1]), "+f"(c[2]), "+f"(c[3])
        : "r"(a0), "r"(a1), "r"(a2), "r"(a3), "r"(b0), "r"(b1));
}

#define CP_ASYNC16(dst_u32, src_ptr) \
    asm volatile("cp.async.cg.shared.global [%0], [%1], 16;" \
                 :: "r"(dst_u32), "l"(src_ptr) : "memory")
#define CP_COMMIT() asm volatile("cp.async.commit_group;" ::: "memory")
#define CP_WAIT1()  asm volatile("cp.async.wait_group 1;" ::: "memory")
#define CP_WAIT0()  asm volatile("cp.async.wait_group 0;" ::: "memory")

// stage one K-half (8 of 16 16B-chunks per row) of a 128-row fp16 tile
__device__ __forceinline__ void stage_half(char* dst, const __half* src,
                                           int tid, int half) {
    #pragma unroll
    for (int i = tid; i < 1024; i += NTHR) {
        int row = i >> 3;
        int cc  = (i & 7) + half * 8;
        uint32_t d = sptr(dst + row * ROWB + cc * 16);
        const char* s = (const char*)(src + (size_t)row * DIM) + cc * 16;
        CP_ASYNC16(d, s);
    }
}

// half2 exp(2s) = p^4, p = 1 + s/2 + s^2/8 + s^3/48 + s^4/384 ~= exp(s/2)
// (|s|<=0.6 off-diag: truncation rel err <= 6e-6; half rounding ~1e-3/elem,
//  decorrelated across elements -> denom rel err ~1e-5)
__device__ __forceinline__ __half2 exp2s_h2(__half2 s) {
    const __half2 c4  = __float2half2_rn(2.60416667e-3f);   // 1/384
    const __half2 c3  = __float2half2_rn(2.08333333e-2f);   // 1/48
    const __half2 c2  = __float2half2_rn(0.125f);
    const __half2 c1  = __float2half2_rn(0.5f);
    const __half2 one = __float2half2_rn(1.0f);
    __half2 p = __hfma2(s, c4, c3);
    p = __hfma2(p, s, c2);
    p = __hfma2(p, s, c1);
    p = __hfma2(p, s, one);   // ~= exp(s/2)
    p = __hmul2(p, p);        // exp(s)
    return __hmul2(p, p);     // exp(2s)
}

// fp16 row store with mma slot permutation
__device__ __forceinline__ void store_row(__half* dstrow, const float* vv, int lane) {
    #pragma unroll
    for (int c = 0; c < 4; c += 2) {
        int k = 4 * lane + c;
        int K16 = k >> 4, pp = (k & 15) >> 1;
        int slot = K16 * 16 + (pp & 3) * 4 + ((pp >> 2) << 1);
        *(__half2*)(dstrow + slot) = __floats2half2_rn(vv[c], vv[c + 1]);
    }
}

// ---------------- k_norm: paired rows (b, b+BATCH) per warp ----------------
__global__ void k_norm(const float* __restrict__ ei, const float* __restrict__ ej) {
    int b    = (blockIdx.x * blockDim.x + threadIdx.x) >> 5;
    int lane = threadIdx.x & 31;
    if (b >= BATCH) return;

    float4 vi = ((const float4*)(ei + (size_t)b * DIM))[lane];
    float4 vj = ((const float4*)(ej + (size_t)b * DIM))[lane];
    float ssi = vi.x*vi.x + vi.y*vi.y + vi.z*vi.z + vi.w*vi.w;
    float ssj = vj.x*vj.x + vj.y*vj.y + vj.z*vj.z + vj.w*vj.w;
    float dt  = vi.x*vj.x + vi.y*vj.y + vi.z*vj.z + vi.w*vj.w;
    #pragma unroll
    for (int o = 16; o; o >>= 1) {
        ssi += __shfl_xor_sync(0xffffffffu, ssi, o);
        ssj += __shfl_xor_sync(0xffffffffu, ssj, o);
        dt  += __shfl_xor_sync(0xffffffffu, dt,  o);
    }
    float ni = fmaxf(sqrtf(ssi), 1e-12f);
    float nj = fmaxf(sqrtf(ssj), 1e-12f);
    if (lane == 0) {
        g_pos[b] = dt / (ni * nj);
        g_denom[b] = 0.0f;
        g_denom[b + BATCH] = 0.0f;
    }
    float si = 1.0f / ni, sj = 1.0f / nj;
    float wi[4] = { vi.x * si, vi.y * si, vi.z * si, vi.w * si };
    float wj[4] = { vj.x * sj, vj.y * sj, vj.z * sj, vj.w * sj };
    store_row(g_zh + (size_t)b * DIM, wi, lane);
    store_row(g_zh + (size_t)(b + BATCH) * DIM, wj, lane);
}

// ---------------- main: symmetric (upper-triangle) fp16 GEMM + half2 exp ----------------
// grid (64, 33): by==0 -> diagonal tile (bi,bi); by 1..32 -> pair {bi, (bi+by)&63}
// (by==32 valid only for bi<32). Row sums -> denom[bi rows]; col sums -> denom[bj rows].
__global__ void __launch_bounds__(NTHR, 2) k_main() {
    const int bi = blockIdx.x;
    const int by = blockIdx.y;
    if (by == 32 && bi >= 32) return;
    const int bj    = (bi + by) & (NTILE - 1);
    const bool diag = (by == 0);

    extern __shared__ char smem[];
    char* As = smem;
    char* Bs = smem + TILE_SMEM;

    const int tid  = threadIdx.x;
    const int wid  = tid >> 5;
    const int lane = tid & 31;
    const int g    = lane >> 2;         // 0..7
    const int q    = lane & 3;          // 0..3
    const int wm   = wid >> 2;          // 0..1  (M warp, 64 rows)
    const int wn   = wid & 3;           // 0..3  (N warp, 32 cols)
    const int rowStart = bi * BM;
    const int colStart = bj * BN;

    const __half* srcA = g_zh + (size_t)rowStart * DIM;
    const __half* srcB = g_zh + (size_t)colStart * DIM;

    // stage both tiles, split by K-half for load/compute overlap
    stage_half(As, srcA, tid, 0);
    stage_half(Bs, srcB, tid, 0);
    CP_COMMIT();
    stage_half(As, srcA, tid, 1);
    stage_half(Bs, srcB, tid, 1);
    CP_COMMIT();

    const ull* As8 = (const ull*)As;
    const ull* Bs8 = (const ull*)Bs;

    float C[4][4][4];
    #pragma unroll
    for (int i = 0; i < 4; i++)
        #pragma unroll
        for (int j = 0; j < 4; j++)
            #pragma unroll
            for (int e = 0; e < 4; e++) C[i][j][e] = 0.0f;

    CP_WAIT1();
    __syncthreads();

    #pragma unroll
    for (int kh = 0; kh < 2; ++kh) {
        if (kh == 1) { CP_WAIT0(); __syncthreads(); }
        #pragma unroll
        for (int ki = 0; ki < 4; ++ki) {
            const int ks = kh * 4 + ki;          // K16-step 0..7
            ull alo[4], ahi[4], bv[4];
            #pragma unroll
            for (int i = 0; i < 4; i++) {
                int r0 = wm * 64 + i * 16 + g;
                alo[i] = As8[r0 * ROW8 + ks * 4 + q];
                ahi[i] = As8[(r0 + 8) * ROW8 + ks * 4 + q];
            }
            #pragma unroll
            for (int j = 0; j < 4; j++) {
                int n0 = wn * 32 + j * 8 + g;
                bv[j] = Bs8[n0 * ROW8 + ks * 4 + q];
            }
            #pragma unroll
            for (int i = 0; i < 4; i++)
                #pragma unroll
                for (int j = 0; j < 4; j++)
                    mma_f16(C[i][j],
                            lo32(alo[i]), lo32(ahi[i]),
                            hi32(alo[i]), hi32(ahi[i]),
                            lo32(bv[j]),  hi32(bv[j]));
        }
    }

    // half2 exp epilogue: lanes of each half2 = (even col, odd col).
    // rs2h[i][rowhalf] accumulates 4 values/lane (<=14); cs2h[j] 8 values/lane (<=27).
    __half2 rs2h[4][2];
    __half2 cs2h[4];
    const __half2 hzero = __float2half2_rn(0.0f);
    #pragma unroll
    for (int i = 0; i < 4; i++) { rs2h[i][0] = hzero; rs2h[i][1] = hzero; }
    #pragma unroll
    for (int j = 0; j < 4; j++) cs2h[j] = hzero;

    #pragma unroll
    for (int i = 0; i < 4; i++)
        #pragma unroll
        for (int j = 0; j < 4; j++) {
            __half2 p0 = exp2s_h2(__floats2half2_rn(C[i][j][0], C[i][j][1]));
            rs2h[i][0] = __hadd2(rs2h[i][0], p0);
            cs2h[j]    = __hadd2(cs2h[j], p0);
            __half2 p1 = exp2s_h2(__floats2half2_rn(C[i][j][2], C[i][j][3]));
            rs2h[i][1] = __hadd2(rs2h[i][1], p1);
            cs2h[j]    = __hadd2(cs2h[j], p1);
        }

    __syncthreads();   // all mma reads of As/Bs done; reuse smem for reductions
    float* red  = (float*)smem;            // [128][4] row partials per wn
    float* redc = (float*)smem + 512;      // [128][2] col partials per wm

    // row sums: reduce over q (cols within quad) in f32
    #pragma unroll
    for (int i = 0; i < 4; i++) {
        #pragma unroll
        for (int h = 0; h < 2; h++) {
            float v = __low2float(rs2h[i][h]) + __high2float(rs2h[i][h]);
            v += __shfl_xor_sync(0xffffffffu, v, 1);
            v += __shfl_xor_sync(0xffffffffu, v, 2);
            if (q == 0) {
                int row = wm * 64 + i * 16 + h * 8 + g;
                red[row * 4 + wn] = v;
            }
        }
    }
    // col sums: reduce over g (rows within warp) in f32
    if (!diag) {
        #pragma unroll
        for (int j = 0; j < 4; j++) {
            float lo = __low2float(cs2h[j]);
            float hi = __high2float(cs2h[j]);
            #pragma unroll
            for (int o = 4; o <= 16; o <<= 1) {
                lo += __shfl_xor_sync(0xffffffffu, lo, o);
                hi += __shfl_xor_sync(0xffffffffu, hi, o);
            }
            if (g == 0) {
                int col = wn * 32 + j * 8 + q * 2;
                redc[col * 2 + wm]       = lo;
                redc[(col + 1) * 2 + wm] = hi;
            }
        }
    }
    __syncthreads();

    if (tid < BM) {
        float s = red[tid * 4] + red[tid * 4 + 1] + red[tid * 4 + 2] + red[tid * 4 + 3];
        if (diag) s -= E2;   // remove diagonal exp(2*sim_rr) ~ e^2
        atomicAdd(&g_denom[rowStart + tid], s);
        if (!diag) {
            float c = redc[tid * 2] + redc[tid * 2 + 1];
            atomicAdd(&g_denom[colStart + tid], c);
        }
    }
}

// ---------------- final loss reduction ----------------
__global__ void k_loss(float* __restrict__ out) {
    int tid = threadIdx.x;
    float s = 0.0f;
    for (int r = tid; r < NROWS; r += 1024) {
        float p = g_pos[(r < BATCH) ? r : (r - BATCH)];
        s += logf(g_denom[r]) - p * INV_T;
    }
    __shared__ float red[1024];
    red[tid] = s;
    __syncthreads();
    #pragma unroll
    for (int st = 512; st; st >>= 1) {
        if (tid < st) red[tid] += red[tid + st];
        __syncthreads();
    }
    if (tid == 0) out[0] = red[0] / (float)NROWS;
}

extern "C" void kernel_launch(void* const* d_in, const int* in_sizes, int n_in,
                              void* d_out, int out_size) {
    const float* emb_i = (const float*)d_in[0];
    const float* emb_j = (const float*)d_in[1];
    float* out = (float*)d_out;
    (void)in_sizes; (void)n_in; (void)out_size;

    cudaFuncSetAttribute(k_main, cudaFuncAttributeMaxDynamicSharedMemorySize,
                         SMEM_TOTAL);

    k_norm<<<BATCH / 8, 256>>>(emb_i, emb_j);
    dim3 grid(NTILE, 33);
    k_main<<<grid, NTHR, SMEM_TOTAL>>>();
    k_loss<<<1, 1024>>>(out);
}